// round 16
// baseline (speedup 1.0000x reference)
#include <cuda_runtime.h>
#include <cuda_bf16.h>
#include <mma.h>
#include <cstdint>
#include <math.h>

using namespace nvcuda;

#define NB 4
#define CCH 256
#define HW 4096

#define LDT 40                  /* k-major tile row stride, elements */
#define LDW 264                 /* row-major-B tile row stride, elements (528B) */
#define OFF_AH 0
#define OFF_AL 10240
#define OFF_BH 20480
#define OFF_BL 40960
#define STGB 61440              /* Ah+Al+Bh+Bl per stage */
#define SM_GEMM (2 * STGB)      /* 122880 B */
#define NTHR 256

typedef wmma::fragment<wmma::matrix_a, 16, 16, 16, __nv_bfloat16, wmma::row_major> FragA;
typedef wmma::fragment<wmma::matrix_b, 16, 16, 16, __nv_bfloat16, wmma::col_major> FragB;
typedef wmma::fragment<wmma::matrix_b, 16, 16, 16, __nv_bfloat16, wmma::row_major> FragBR;
typedef wmma::fragment<wmma::accumulator, 16, 16, 16, float> FragC;

/* ---------------- scratch (no cudaMalloc allowed) ---------------- */
#define SZ_CN ((size_t)NB * CCH * HW)
#define SZ_EE ((size_t)NB * HW * HW)
static __device__ __align__(16) __nv_bfloat16 g_ex_h[SZ_CN], g_ex_l[SZ_CN];
static __device__ __align__(16) __nv_bfloat16 g_q_h[SZ_CN],  g_q_l[SZ_CN];
static __device__ __align__(16) __nv_bfloat16 g_ext_h[SZ_CN], g_ext_l[SZ_CN];
static __device__ __align__(16) __nv_bfloat16 g_qt_h[SZ_CN],  g_qt_l[SZ_CN];
static __device__ __align__(16) __nv_bfloat16 g_We_h[CCH*CCH], g_We_l[CCH*CCH];
static __device__ __align__(16) __nv_bfloat16 g_W1_h[CCH*2*CCH], g_W1_l[CCH*2*CCH];
static __device__ __align__(16) __nv_bfloat16 g_W2_h[CCH*2*CCH], g_W2_l[CCH*2*CCH];
static __device__ __align__(16) __nv_bfloat16 g_ec_h[SZ_CN], g_ec_l[SZ_CN];
static __device__ __align__(16) __nv_bfloat16 g_En_h[SZ_EE], g_En_l[SZ_EE];
static __device__ __align__(16) __nv_bfloat16 g_qatt_h[SZ_CN], g_qatt_l[SZ_CN];
static __device__ __align__(16) __nv_bfloat16 g_eatt_h[SZ_CN], g_eatt_l[SZ_CN];
static __device__ __align__(16) float g_qattF[SZ_CN], g_eattF[SZ_CN];
static __device__ float g_colsum[NB*HW], g_rowsum[NB*HW];

__device__ __forceinline__ uint32_t s2u(const void* p) {
    uint32_t a;
    asm("{ .reg .u64 t; cvta.to.shared.u64 t, %1; cvt.u32.u64 %0, t; }" : "=r"(a) : "l"(p));
    return a;
}
__device__ __forceinline__ void cpa16(uint32_t d, const void* g) {
    asm volatile("cp.async.cg.shared.global [%0], [%1], 16;" :: "r"(d), "l"(g));
}

/* ==== wmma 128x256 CTA-tile GEMM: 8 warps (2x4) x 64x64, merged 3-product split ==== */
/* acc += Ah.Bh + Ah.Bl + Al.Bh.  BROW=0: B k-major [c][k]. BROW=1: B row-major [k][c]. */
template <bool BROW>
__device__ void gemm_core(char* sm, uint32_t smu,
    const __nv_bfloat16* Ah, const __nv_bfloat16* Al, int lda,
    const __nv_bfloat16* B1h, const __nv_bfloat16* B1l,
    const __nv_bfloat16* B2h, const __nv_bfloat16* B2l, int ksplit, int ldb,
    int K, FragC (&acc)[4][4])
{
    const int t = threadIdx.x, wid = t >> 5;
    const int wm = wid >> 2, wn = wid & 3;  /* 2x4 warps: 64x64 tile each */
    const int nch = K / 32;

#pragma unroll
    for (int mf = 0; mf < 4; ++mf)
#pragma unroll
        for (int nf = 0; nf < 4; ++nf)
            wmma::fill_fragment(acc[mf][nf], 0.0f);

    auto issue = [&](int it) {
        int k0 = it * 32;
        const __nv_bfloat16* ah = Ah + k0;
        const __nv_bfloat16* al = Al + k0;
        const __nv_bfloat16* ph = B1h; const __nv_bfloat16* pl = B1l; int kb = k0;
        if (k0 >= ksplit) { ph = B2h; pl = B2l; kb = k0 - ksplit; }
        const __nv_bfloat16* bh = BROW ? ph + (size_t)kb * ldb : ph + kb;
        const __nv_bfloat16* bl = BROW ? pl + (size_t)kb * ldb : pl + kb;
        uint32_t buf = (uint32_t)(it & 1) * STGB;
#pragma unroll
        for (int i = 0; i < 4; ++i) {
            int v = t + i * NTHR;
            if (i < 2) {  /* A: 128x32, 512 vec16 per dtype */
                int r = v >> 2, c = v & 3;
                cpa16(smu + buf + OFF_AH + r * (LDT * 2) + c * 16, ah + (size_t)r * lda + c * 8);
                cpa16(smu + buf + OFF_AL + r * (LDT * 2) + c * 16, al + (size_t)r * lda + c * 8);
            }
            if (BROW) {   /* B: 32 rows x 256 cols, 1024 vec16 per dtype */
                int rb = v >> 5, cb = v & 31;
                cpa16(smu + buf + OFF_BH + rb * (LDW * 2) + cb * 16, bh + (size_t)rb * ldb + cb * 8);
                cpa16(smu + buf + OFF_BL + rb * (LDW * 2) + cb * 16, bl + (size_t)rb * ldb + cb * 8);
            } else {      /* B: 256 rows x 32k, 1024 vec16 per dtype */
                int r = v >> 2, c = v & 3;
                cpa16(smu + buf + OFF_BH + r * (LDT * 2) + c * 16, bh + (size_t)r * ldb + c * 8);
                cpa16(smu + buf + OFF_BL + r * (LDT * 2) + c * 16, bl + (size_t)r * ldb + c * 8);
            }
        }
        asm volatile("cp.async.commit_group;" ::: "memory");
    };
    auto comp = [&](int stg) {
        const __nv_bfloat16* Ahs = (const __nv_bfloat16*)(sm + stg * STGB + OFF_AH);
        const __nv_bfloat16* Als = (const __nv_bfloat16*)(sm + stg * STGB + OFF_AL);
        const __nv_bfloat16* Bhs = (const __nv_bfloat16*)(sm + stg * STGB + OFF_BH);
        const __nv_bfloat16* Bls = (const __nv_bfloat16*)(sm + stg * STGB + OFF_BL);
#pragma unroll
        for (int kk = 0; kk < 32; kk += 16) {
            FragA afh[4], afl[4];
#pragma unroll
            for (int mf = 0; mf < 4; ++mf) {
                wmma::load_matrix_sync(afh[mf], Ahs + (wm * 64 + mf * 16) * LDT + kk, LDT);
                wmma::load_matrix_sync(afl[mf], Als + (wm * 64 + mf * 16) * LDT + kk, LDT);
            }
            if (BROW) {
#pragma unroll
                for (int nf = 0; nf < 4; ++nf) {
                    FragBR bh, bl;
                    wmma::load_matrix_sync(bh, Bhs + kk * LDW + wn * 64 + nf * 16, LDW);
                    wmma::load_matrix_sync(bl, Bls + kk * LDW + wn * 64 + nf * 16, LDW);
#pragma unroll
                    for (int mf = 0; mf < 4; ++mf) {
                        wmma::mma_sync(acc[mf][nf], afh[mf], bh, acc[mf][nf]);
                        wmma::mma_sync(acc[mf][nf], afh[mf], bl, acc[mf][nf]);
                        wmma::mma_sync(acc[mf][nf], afl[mf], bh, acc[mf][nf]);
                    }
                }
            } else {
#pragma unroll
                for (int nf = 0; nf < 4; ++nf) {
                    FragB bh, bl;
                    wmma::load_matrix_sync(bh, Bhs + (wn * 64 + nf * 16) * LDT + kk, LDT);
                    wmma::load_matrix_sync(bl, Bls + (wn * 64 + nf * 16) * LDT + kk, LDT);
#pragma unroll
                    for (int mf = 0; mf < 4; ++mf) {
                        wmma::mma_sync(acc[mf][nf], afh[mf], bh, acc[mf][nf]);
                        wmma::mma_sync(acc[mf][nf], afh[mf], bl, acc[mf][nf]);
                        wmma::mma_sync(acc[mf][nf], afl[mf], bh, acc[mf][nf]);
                    }
                }
            }
        }
    };

    issue(0);
    for (int it = 0; it < nch; ++it) {
        if (it + 1 < nch) {
            issue(it + 1);
            asm volatile("cp.async.wait_group 1;" ::: "memory");
        } else {
            asm volatile("cp.async.wait_group 0;" ::: "memory");
        }
        __syncthreads();
        comp(it & 1);
        __syncthreads();
    }
}

__device__ __forceinline__ void store_c(FragC (&acc)[4][4], float* C, int ldc)
{
    int wid = threadIdx.x >> 5, wm = wid >> 2, wn = wid & 3;
#pragma unroll
    for (int mf = 0; mf < 4; ++mf)
#pragma unroll
        for (int nf = 0; nf < 4; ++nf)
            wmma::store_matrix_sync(C + (size_t)(wm * 64 + mf * 16) * ldc + wn * 64 + nf * 16,
                                    acc[mf][nf], ldc, wmma::mem_row_major);
}
__device__ __forceinline__ void store_c_col(FragC (&acc)[4][4], float* C, int ldc)
{
    int wid = threadIdx.x >> 5, wm = wid >> 2, wn = wid & 3;
#pragma unroll
    for (int mf = 0; mf < 4; ++mf)
#pragma unroll
        for (int nf = 0; nf < 4; ++nf)
            wmma::store_matrix_sync(C + (size_t)(wn * 64 + nf * 16) * ldc + wm * 64 + mf * 16,
                                    acc[mf][nf], ldc, wmma::mem_col_major);
}

/* ---- epilogue: stage 64-row halves (64x264 fp32), write hi/lo split; 256 thr ---- */
__device__ void epilogue_split(char* sm, FragC (&acc)[4][4],
    __nv_bfloat16* dh, __nv_bfloat16* dl, size_t rowbase, int ldo)
{
    int t = threadIdx.x, wid = t >> 5, wm = wid >> 2, wn = wid & 3;
    float* stg = (float*)sm;
    const int LDS2 = 264;
    for (int h = 0; h < 2; ++h) {
        __syncthreads();
        if (wm == h) {
#pragma unroll
            for (int mf = 0; mf < 4; ++mf)
#pragma unroll
                for (int nf = 0; nf < 4; ++nf)
                    wmma::store_matrix_sync(stg + (mf * 16) * LDS2 + wn * 64 + nf * 16,
                                            acc[mf][nf], LDS2, wmma::mem_row_major);
        }
        __syncthreads();
        int row = t >> 2, seg = t & 3;   /* 64 rows x 4 segments of 64 */
        const float* sp = stg + row * LDS2 + seg * 64;
        size_t o = rowbase + (size_t)(h * 64 + row) * ldo + seg * 64;
#pragma unroll
        for (int q = 0; q < 8; ++q) {
            __nv_bfloat162 hv[4], lv[4];
#pragma unroll
            for (int j = 0; j < 4; ++j) {
                float a = sp[q * 8 + 2 * j], c2 = sp[q * 8 + 2 * j + 1];
                __nv_bfloat16 ha = __float2bfloat16(a), hc = __float2bfloat16(c2);
                hv[j].x = ha; hv[j].y = hc;
                lv[j].x = __float2bfloat16(a - __bfloat162float(ha));
                lv[j].y = __float2bfloat16(c2 - __bfloat162float(hc));
            }
            *(uint4*)(dh + o + q * 8) = *(uint4*)hv;
            *(uint4*)(dl + o + q * 8) = *(uint4*)lv;
        }
    }
}

/* ---------------- GEMM1: ec[n][0:256] = ext[n][:] . We ---------------- */
__global__ __launch_bounds__(NTHR, 1) void k_g1()
{
    extern __shared__ __align__(128) char sm[];
    uint32_t smu = s2u(sm);
    int b = blockIdx.z, r0 = blockIdx.y * 128;
    FragC acc[4][4];
    size_t ao = ((size_t)b * HW + r0) * CCH;
    gemm_core<false>(sm, smu, g_ext_h + ao, g_ext_l + ao, CCH,
              g_We_h, g_We_l, g_We_h, g_We_l, 1 << 30, CCH, CCH, acc);
    epilogue_split(sm, acc, g_ec_h, g_ec_l, ao, CCH);
}

/* ---- GEMM2 + fused epilogue: E=__expf(ec.qt^T); En hi/lo; row/col sums ---- */
__global__ __launch_bounds__(NTHR, 1) void k_g2()
{
    extern __shared__ __align__(128) char sm[];
    uint32_t smu = s2u(sm);
    int b = blockIdx.z, r0 = blockIdx.y * 128, c0 = blockIdx.x * 256;
    int t = threadIdx.x, wid = t >> 5, wm = wid >> 2, wn = wid & 3;
    FragC acc[4][4];
    size_t ao = ((size_t)b * HW + r0) * CCH, bo = ((size_t)b * HW + c0) * CCH;
    gemm_core<false>(sm, smu, g_ec_h + ao, g_ec_l + ao, CCH,
              g_qt_h + bo, g_qt_l + bo, g_qt_h + bo, g_qt_l + bo, 1 << 30, CCH, CCH, acc);

#pragma unroll
    for (int mf = 0; mf < 4; ++mf)
#pragma unroll
        for (int nf = 0; nf < 4; ++nf)
#pragma unroll
            for (int i = 0; i < acc[mf][nf].num_elements; ++i)
                acc[mf][nf].x[i] = __expf(acc[mf][nf].x[i]);

    float* stg = (float*)sm;
    const int LDS2 = 264;
    float csum = 0.f;
    for (int h = 0; h < 2; ++h) {
        __syncthreads();
        if (wm == h) {
#pragma unroll
            for (int mf = 0; mf < 4; ++mf)
#pragma unroll
                for (int nf = 0; nf < 4; ++nf)
                    wmma::store_matrix_sync(stg + (mf * 16) * LDS2 + wn * 64 + nf * 16,
                                            acc[mf][nf], LDS2, wmma::mem_row_major);
        }
        __syncthreads();
        {
            int row = t >> 2, seg = t & 3;
            const float* sp = stg + row * LDS2 + seg * 64;
            size_t o = ((size_t)b * HW + r0 + h * 64 + row) * HW + c0 + seg * 64;
            float rs = 0.f;
#pragma unroll
            for (int q = 0; q < 8; ++q) {
                __nv_bfloat162 hv[4], lv[4];
#pragma unroll
                for (int j = 0; j < 4; ++j) {
                    float a = sp[q * 8 + 2 * j], c2 = sp[q * 8 + 2 * j + 1];
                    rs += a + c2;
                    __nv_bfloat16 ha = __float2bfloat16(a), hc = __float2bfloat16(c2);
                    hv[j].x = ha; hv[j].y = hc;
                    lv[j].x = __float2bfloat16(a - __bfloat162float(ha));
                    lv[j].y = __float2bfloat16(c2 - __bfloat162float(hc));
                }
                *(uint4*)(g_En_h + o + q * 8) = *(uint4*)hv;
                *(uint4*)(g_En_l + o + q * 8) = *(uint4*)lv;
            }
            rs += __shfl_xor_sync(~0u, rs, 1);
            rs += __shfl_xor_sync(~0u, rs, 2);
            if (seg == 0) atomicAdd(&g_rowsum[b * HW + r0 + h * 64 + row], rs);
        }
        {
            const float* sp = stg + t;
#pragma unroll
            for (int j = 0; j < 64; ++j) csum += sp[j * LDS2];
        }
    }
    atomicAdd(&g_colsum[b * HW + c0 + t], csum);
}

/* ------ GEMM3/4 merged: grid (32,1,NB*2); z -> (b, sel) ------ */
__global__ __launch_bounds__(NTHR, 1) void k_att()
{
    extern __shared__ __align__(128) char sm[];
    uint32_t smu = s2u(sm);
    int z = blockIdx.z, b = z >> 1, sel = z & 1, bx = blockIdx.x;
    FragC acc[4][4];
    if (sel == 1) {
        /* eattF[r0..+128][0:256] = En[r][:] . q[c][:] */
        int r0 = bx * 128;
        size_t ao = ((size_t)b * HW + r0) * HW, bo = (size_t)b * CCH * HW;
        gemm_core<false>(sm, smu, g_En_h + ao, g_En_l + ao, HW,
                  g_q_h + bo, g_q_l + bo, g_q_h + bo, g_q_l + bo, 1 << 30, HW, HW, acc);
        __syncthreads();
        store_c(acc, g_eattF + ((size_t)b * HW + r0) * CCH, CCH);
    } else {
        /* C[cblk..+128][m0..+256] = ex[c][:] . En[:][m]; col-major -> qattF[m][c] */
        int cblk = (bx & 1) * 128, m0 = (bx >> 1) * 256;
        size_t ao = ((size_t)b * CCH + cblk) * HW;
        const __nv_bfloat16* Bh = g_En_h + (size_t)b * HW * HW + m0;
        const __nv_bfloat16* Bl = g_En_l + (size_t)b * HW * HW + m0;
        gemm_core<true>(sm, smu, g_ex_h + ao, g_ex_l + ao, HW,
                  Bh, Bl, Bh, Bl, 1 << 30, HW, HW, acc);
        __syncthreads();
        store_c_col(acc, g_qattF + ((size_t)b * HW + m0) * CCH + cblk, CCH);
    }
}

/* ------ conv merged: out[o0..+128][x0..+256]; z -> (b, w) ------ */
__global__ __launch_bounds__(NTHR, 1) void k_conv(float* __restrict__ out)
{
    extern __shared__ __align__(128) char sm[];
    uint32_t smu = s2u(sm);
    int z = blockIdx.z, b = z >> 1, w = z & 1;
    int o0 = blockIdx.y * 128, x0 = blockIdx.x * 256;
    const __nv_bfloat16 *Wh, *Wl, *B1h, *B1l, *B2h, *B2l;
    if (w == 0) { Wh = g_W1_h; Wl = g_W1_l; B1h = g_eatt_h; B1l = g_eatt_l; B2h = g_ext_h; B2l = g_ext_l; }
    else        { Wh = g_W2_h; Wl = g_W2_l; B1h = g_qatt_h; B1l = g_qatt_l; B2h = g_qt_h;  B2l = g_qt_l; }
    FragC acc[4][4];
    size_t bo = ((size_t)b * HW + x0) * CCH;
    gemm_core<false>(sm, smu, Wh + (size_t)o0 * 512, Wl + (size_t)o0 * 512, 512,
              B1h + bo, B1l + bo, B2h + bo, B2l + bo, 256, CCH, 512, acc);
    __syncthreads();
    store_c(acc, out + (size_t)w * SZ_CN + ((size_t)b * CCH + o0) * HW + x0, HW);
}

/* ---------------- ew3 merged: normalize + gate + split; y -> sel ---------------- */
__global__ __launch_bounds__(256) void k_ew3(const float* __restrict__ gw)
{
    __shared__ float sgw[256];
    int tid = threadIdx.x, lane = tid & 31, wid = tid >> 5;
    int sel = blockIdx.y;
    sgw[tid] = gw[tid];
    __syncthreads();
    const float* af = sel ? g_eattF : g_qattF;
    const float* sums = sel ? g_rowsum : g_colsum;
    __nv_bfloat16* oh = sel ? g_eatt_h : g_qatt_h;
    __nv_bfloat16* ol = sel ? g_eatt_l : g_qatt_l;
    size_t row = (size_t)blockIdx.x * 8 + wid;
    float4 v0 = *(const float4*)(af + row * 256 + lane * 8);
    float4 v1 = *(const float4*)(af + row * 256 + lane * 8 + 4);
    float v[8] = {v0.x, v0.y, v0.z, v0.w, v1.x, v1.y, v1.z, v1.w};
    float dot = 0.f;
#pragma unroll
    for (int j = 0; j < 8; ++j) dot += v[j] * sgw[lane * 8 + j];
#pragma unroll
    for (int m = 16; m; m >>= 1) dot += __shfl_xor_sync(~0u, dot, m);
    float inv = 1.f / sums[row];
    float s = inv / (1.f + expf(-inv * dot));
    __nv_bfloat162 hq[4], lq[4];
#pragma unroll
    for (int j = 0; j < 4; ++j) {
        float a = v[2 * j] * s, c = v[2 * j + 1] * s;
        __nv_bfloat16 ha = __float2bfloat16(a), hc = __float2bfloat16(c);
        hq[j].x = ha; hq[j].y = hc;
        lq[j].x = __float2bfloat16(a - __bfloat162float(ha));
        lq[j].y = __float2bfloat16(c - __bfloat162float(hc));
    }
    *(uint4*)(oh + row * 256 + lane * 8) = *(uint4*)hq;
    *(uint4*)(ol + row * 256 + lane * 8) = *(uint4*)lq;
}

/* ---------------- prep1: ALL linear splits + zero, one launch ---------------- */
#define N2IN ((int)(SZ_CN / 2))
__global__ void k_prep1(const float* __restrict__ in1, const float* __restrict__ in2,
                        const float* __restrict__ We, const float* __restrict__ W1,
                        const float* __restrict__ W2)
{
    int idx = blockIdx.x * 256 + threadIdx.x;
    const float* src; __nv_bfloat16 *dh, *dl; int i = idx;
    if (idx < N2IN)                         { src = in1; dh = g_ex_h; dl = g_ex_l; }
    else if ((i -= N2IN) < N2IN)            { src = in2; dh = g_q_h;  dl = g_q_l;  }
    else if ((i -= N2IN) < CCH*CCH/2)       { src = We;  dh = g_We_h; dl = g_We_l; }
    else if ((i -= CCH*CCH/2) < CCH*CCH)    { src = W1;  dh = g_W1_h; dl = g_W1_l; }
    else if ((i -= CCH*CCH) < CCH*CCH)      { src = W2;  dh = g_W2_h; dl = g_W2_l; }
    else {
        i -= CCH*CCH;
        if (i < NB * HW) { g_colsum[i] = 0.f; g_rowsum[i] = 0.f; }
        return;
    }
    float2 v = ((const float2*)src)[i];
    __nv_bfloat16 h0 = __float2bfloat16(v.x), h1 = __float2bfloat16(v.y);
    __nv_bfloat162 hp, lp;
    hp.x = h0; hp.y = h1;
    lp.x = __float2bfloat16(v.x - __bfloat162float(h0));
    lp.y = __float2bfloat16(v.y - __bfloat162float(h1));
    ((__nv_bfloat162*)dh)[i] = hp;
    ((__nv_bfloat162*)dl)[i] = lp;
}
#define PREP1_TOTAL (2 * N2IN + CCH*CCH/2 + 2 * CCH*CCH + NB * HW)

/* ---------------- tsplit both inputs: z = sel*NB + b ---------------- */
__global__ void k_tsplit(const float* __restrict__ in1, const float* __restrict__ in2)
{
    __shared__ float t[32][33];
    int z = blockIdx.z, sel = z / NB, b = z % NB;
    const float* src = sel ? in2 : in1;
    __nv_bfloat16* dh = sel ? g_qt_h : g_ext_h;
    __nv_bfloat16* dl = sel ? g_qt_l : g_ext_l;
    int c0 = blockIdx.y * 32, n0 = blockIdx.x * 32;
    int tx = threadIdx.x, ty = threadIdx.y;
#pragma unroll
    for (int i = 0; i < 4; ++i)
        t[ty + i * 8][tx] = src[((size_t)b * CCH + c0 + ty + i * 8) * HW + n0 + tx];
    __syncthreads();
#pragma unroll
    for (int i = 0; i < 4; ++i) {
        float v = t[tx][ty + i * 8];
        size_t o = ((size_t)b * HW + n0 + ty + i * 8) * CCH + c0 + tx;
        __nv_bfloat16 h = __float2bfloat16(v);
        dh[o] = h;
        dl[o] = __float2bfloat16(v - __bfloat162float(h));
    }
}

/* ---------------- launch ---------------- */
extern "C" void kernel_launch(void* const* d_in, const int* in_sizes, int n_in,
                              void* d_out, int out_size)
{
    const float* in1 = (const float*)d_in[0];
    const float* in2 = (const float*)d_in[1];
    const float* We  = (const float*)d_in[2];
    const float* gw  = (const float*)d_in[3];
    const float* W1  = (const float*)d_in[4];
    const float* W2  = (const float*)d_in[5];
    float* out = (float*)d_out;

    cudaFuncSetAttribute(k_g1,   cudaFuncAttributeMaxDynamicSharedMemorySize, SM_GEMM);
    cudaFuncSetAttribute(k_g2,   cudaFuncAttributeMaxDynamicSharedMemorySize, SM_GEMM);
    cudaFuncSetAttribute(k_att,  cudaFuncAttributeMaxDynamicSharedMemorySize, SM_GEMM);
    cudaFuncSetAttribute(k_conv, cudaFuncAttributeMaxDynamicSharedMemorySize, SM_GEMM);

    k_prep1<<<(PREP1_TOTAL + 255) / 256, 256>>>(in1, in2, We, W1, W2);           /* #1 */
    k_tsplit<<<dim3(HW / 32, CCH / 32, NB * 2), dim3(32, 8)>>>(in1, in2);        /* #2 */
    k_g1<<<dim3(1, HW / 128, NB), NTHR, SM_GEMM>>>();                            /* #3 */
    k_g2<<<dim3(HW / 256, HW / 128, NB), NTHR, SM_GEMM>>>();                     /* #4 <- ncu */
    k_att<<<dim3(32, 1, NB * 2), NTHR, SM_GEMM>>>();                             /* #5 */
    k_ew3<<<dim3(NB * HW / 8, 2), 256>>>(gw);                                    /* #6 */
    k_conv<<<dim3(HW / 256, CCH / 128, NB * 2), NTHR, SM_GEMM>>>(out);           /* #7 */
}

// round 17
// speedup vs baseline: 1.0611x; 1.0611x over previous
#include <cuda_runtime.h>
#include <cuda_bf16.h>
#include <mma.h>
#include <cstdint>
#include <math.h>

using namespace nvcuda;

#define NB 4
#define CCH 256
#define HW 4096

#define LDT 40                  /* k-major tile row stride, elements */
#define LDW 136                 /* row-major-B tile row stride, elements (272B) */
#define TILEA 10240             /* bytes per operand tile slot */
#define STGB (4 * TILEA)        /* Ah+Al+Bh+Bl per stage = 40960 B */
#define NSTG 2
#define SM_GEMM (NSTG * STGB)   /* 81920 B */
#define NTHR 128

typedef wmma::fragment<wmma::matrix_a, 16, 16, 16, __nv_bfloat16, wmma::row_major> FragA;
typedef wmma::fragment<wmma::matrix_b, 16, 16, 16, __nv_bfloat16, wmma::col_major> FragB;
typedef wmma::fragment<wmma::matrix_b, 16, 16, 16, __nv_bfloat16, wmma::row_major> FragBR;
typedef wmma::fragment<wmma::accumulator, 16, 16, 16, float> FragC;

/* ---------------- scratch (no cudaMalloc allowed) ---------------- */
#define SZ_CN ((size_t)NB * CCH * HW)
#define SZ_EE ((size_t)NB * HW * HW)
static __device__ __align__(16) __nv_bfloat16 g_ex_h[SZ_CN], g_ex_l[SZ_CN];
static __device__ __align__(16) __nv_bfloat16 g_q_h[SZ_CN],  g_q_l[SZ_CN];
static __device__ __align__(16) __nv_bfloat16 g_ext_h[SZ_CN], g_ext_l[SZ_CN];
static __device__ __align__(16) __nv_bfloat16 g_qt_h[SZ_CN],  g_qt_l[SZ_CN];
static __device__ __align__(16) __nv_bfloat16 g_We_h[CCH*CCH], g_We_l[CCH*CCH];
static __device__ __align__(16) __nv_bfloat16 g_W1_h[CCH*2*CCH], g_W1_l[CCH*2*CCH];
static __device__ __align__(16) __nv_bfloat16 g_W2_h[CCH*2*CCH], g_W2_l[CCH*2*CCH];
static __device__ __align__(16) __nv_bfloat16 g_ec_h[SZ_CN], g_ec_l[SZ_CN];
static __device__ __align__(16) __nv_bfloat16 g_En_h[SZ_EE], g_En_l[SZ_EE];
static __device__ __align__(16) __nv_bfloat16 g_qatt_h[SZ_CN], g_qatt_l[SZ_CN];
static __device__ __align__(16) __nv_bfloat16 g_eatt_h[SZ_CN], g_eatt_l[SZ_CN];
static __device__ __align__(16) float g_qattF[SZ_CN], g_eattF[SZ_CN];
static __device__ float g_colsum[NB*HW], g_rowsum[NB*HW];

__device__ __forceinline__ uint32_t s2u(const void* p) {
    uint32_t a;
    asm("{ .reg .u64 t; cvta.to.shared.u64 t, %1; cvt.u32.u64 %0, t; }" : "=r"(a) : "l"(p));
    return a;
}
__device__ __forceinline__ void cpa16(uint32_t d, const void* g) {
    asm volatile("cp.async.cg.shared.global [%0], [%1], 16;" :: "r"(d), "l"(g));
}

/* ==== wmma 128x128 GEMM core: single K-sweep, merged 3-product split-bf16 ==== */
/* acc += Ah.Bh + Ah.Bl + Al.Bh; pass-major MMA order over nf-pairs for ILP.   */
template <bool BROW>
__device__ void gemm_core(char* sm, uint32_t smu,
    const __nv_bfloat16* Ah, const __nv_bfloat16* Al, int lda,
    const __nv_bfloat16* B1h, const __nv_bfloat16* B1l,
    const __nv_bfloat16* B2h, const __nv_bfloat16* B2l, int ksplit, int ldb,
    int K, FragC (&acc)[4][4])
{
    const int t = threadIdx.x, wid = t >> 5;
    const int wm = wid >> 1, wn = wid & 1;  /* 2x2 warps: 64x64 tile each */
    const int nch = K / 32;

#pragma unroll
    for (int mf = 0; mf < 4; ++mf)
#pragma unroll
        for (int nf = 0; nf < 4; ++nf)
            wmma::fill_fragment(acc[mf][nf], 0.0f);

    auto issue = [&](int it) {
        int k0 = it * 32;
        const __nv_bfloat16* ah = Ah + k0;
        const __nv_bfloat16* al = Al + k0;
        const __nv_bfloat16* ph = B1h; const __nv_bfloat16* pl = B1l; int kb = k0;
        if (k0 >= ksplit) { ph = B2h; pl = B2l; kb = k0 - ksplit; }
        const __nv_bfloat16* bh = BROW ? ph + (size_t)kb * ldb : ph + kb;
        const __nv_bfloat16* bl = BROW ? pl + (size_t)kb * ldb : pl + kb;
        uint32_t buf = (uint32_t)(it & 1) * STGB;
#pragma unroll
        for (int i = 0; i < 4; ++i) {
            int v = t + i * NTHR;
            int r = v >> 2, c = v & 3;
            cpa16(smu + buf + r * (LDT * 2) + c * 16, ah + (size_t)r * lda + c * 8);
            cpa16(smu + buf + TILEA + r * (LDT * 2) + c * 16, al + (size_t)r * lda + c * 8);
            if (BROW) {
                int rb = v >> 4, cb = v & 15;
                cpa16(smu + buf + 2 * TILEA + rb * (LDW * 2) + cb * 16, bh + (size_t)rb * ldb + cb * 8);
                cpa16(smu + buf + 3 * TILEA + rb * (LDW * 2) + cb * 16, bl + (size_t)rb * ldb + cb * 8);
            } else {
                cpa16(smu + buf + 2 * TILEA + r * (LDT * 2) + c * 16, bh + (size_t)r * ldb + c * 8);
                cpa16(smu + buf + 3 * TILEA + r * (LDT * 2) + c * 16, bl + (size_t)r * ldb + c * 8);
            }
        }
        asm volatile("cp.async.commit_group;" ::: "memory");
    };
    auto comp = [&](int stg) {
        const __nv_bfloat16* Ahs = (const __nv_bfloat16*)(sm + stg * STGB);
        const __nv_bfloat16* Als = (const __nv_bfloat16*)(sm + stg * STGB + TILEA);
        const __nv_bfloat16* Bhs = (const __nv_bfloat16*)(sm + stg * STGB + 2 * TILEA);
        const __nv_bfloat16* Bls = (const __nv_bfloat16*)(sm + stg * STGB + 3 * TILEA);
#pragma unroll
        for (int kk = 0; kk < 32; kk += 16) {
            FragA afh[4], afl[4];
#pragma unroll
            for (int mf = 0; mf < 4; ++mf) {
                wmma::load_matrix_sync(afh[mf], Ahs + (wm * 64 + mf * 16) * LDT + kk, LDT);
                wmma::load_matrix_sync(afl[mf], Als + (wm * 64 + mf * 16) * LDT + kk, LDT);
            }
#pragma unroll
            for (int nfp = 0; nfp < 4; nfp += 2) {
                if (BROW) {
                    FragBR bh[2], bl[2];
#pragma unroll
                    for (int j = 0; j < 2; ++j) {
                        wmma::load_matrix_sync(bh[j], Bhs + kk * LDW + wn * 64 + (nfp + j) * 16, LDW);
                        wmma::load_matrix_sync(bl[j], Bls + kk * LDW + wn * 64 + (nfp + j) * 16, LDW);
                    }
#pragma unroll
                    for (int j = 0; j < 2; ++j)
#pragma unroll
                        for (int mf = 0; mf < 4; ++mf)
                            wmma::mma_sync(acc[mf][nfp + j], afh[mf], bh[j], acc[mf][nfp + j]);
#pragma unroll
                    for (int j = 0; j < 2; ++j)
#pragma unroll
                        for (int mf = 0; mf < 4; ++mf)
                            wmma::mma_sync(acc[mf][nfp + j], afh[mf], bl[j], acc[mf][nfp + j]);
#pragma unroll
                    for (int j = 0; j < 2; ++j)
#pragma unroll
                        for (int mf = 0; mf < 4; ++mf)
                            wmma::mma_sync(acc[mf][nfp + j], afl[mf], bh[j], acc[mf][nfp + j]);
                } else {
                    FragB bh[2], bl[2];
#pragma unroll
                    for (int j = 0; j < 2; ++j) {
                        wmma::load_matrix_sync(bh[j], Bhs + (wn * 64 + (nfp + j) * 16) * LDT + kk, LDT);
                        wmma::load_matrix_sync(bl[j], Bls + (wn * 64 + (nfp + j) * 16) * LDT + kk, LDT);
                    }
#pragma unroll
                    for (int j = 0; j < 2; ++j)
#pragma unroll
                        for (int mf = 0; mf < 4; ++mf)
                            wmma::mma_sync(acc[mf][nfp + j], afh[mf], bh[j], acc[mf][nfp + j]);
#pragma unroll
                    for (int j = 0; j < 2; ++j)
#pragma unroll
                        for (int mf = 0; mf < 4; ++mf)
                            wmma::mma_sync(acc[mf][nfp + j], afh[mf], bl[j], acc[mf][nfp + j]);
#pragma unroll
                    for (int j = 0; j < 2; ++j)
#pragma unroll
                        for (int mf = 0; mf < 4; ++mf)
                            wmma::mma_sync(acc[mf][nfp + j], afl[mf], bh[j], acc[mf][nfp + j]);
                }
            }
        }
    };

    issue(0);
    for (int it = 0; it < nch; ++it) {
        if (it + 1 < nch) {
            issue(it + 1);
            asm volatile("cp.async.wait_group 1;" ::: "memory");
        } else {
            asm volatile("cp.async.wait_group 0;" ::: "memory");
        }
        __syncthreads();
        comp(it & 1);
        __syncthreads();
    }
}

__device__ __forceinline__ void store_c(FragC (&acc)[4][4], float* C, int ldc)
{
    int wid = threadIdx.x >> 5, wm = wid >> 1, wn = wid & 1;
#pragma unroll
    for (int mf = 0; mf < 4; ++mf)
#pragma unroll
        for (int nf = 0; nf < 4; ++nf)
            wmma::store_matrix_sync(C + (size_t)(wm * 64 + mf * 16) * ldc + wn * 64 + nf * 16,
                                    acc[mf][nf], ldc, wmma::mem_row_major);
}
__device__ __forceinline__ void store_c_col(FragC (&acc)[4][4], float* C, int ldc)
{
    int wid = threadIdx.x >> 5, wm = wid >> 1, wn = wid & 1;
#pragma unroll
    for (int mf = 0; mf < 4; ++mf)
#pragma unroll
        for (int nf = 0; nf < 4; ++nf)
            wmma::store_matrix_sync(C + (size_t)(wn * 64 + nf * 16) * ldc + wm * 64 + mf * 16,
                                    acc[mf][nf], ldc, wmma::mem_col_major);
}

/* ---- epilogue: stage 64-row halves, write hi/lo split, 128 threads ---- */
__device__ void epilogue_split(char* sm, FragC (&acc)[4][4],
    __nv_bfloat16* dh, __nv_bfloat16* dl, size_t rowbase, int ldo)
{
    int t = threadIdx.x, wid = t >> 5, wm = wid >> 1, wn = wid & 1;
    float* stg = (float*)sm;
    const int LDS2 = 132;
    for (int h = 0; h < 2; ++h) {
        __syncthreads();
        if (wm == h) {
#pragma unroll
            for (int mf = 0; mf < 4; ++mf)
#pragma unroll
                for (int nf = 0; nf < 4; ++nf)
                    wmma::store_matrix_sync(stg + (mf * 16) * LDS2 + wn * 64 + nf * 16,
                                            acc[mf][nf], LDS2, wmma::mem_row_major);
        }
        __syncthreads();
        int row = t >> 1, seg = t & 1;
        const float* sp = stg + row * LDS2 + seg * 64;
        size_t o = rowbase + (size_t)(h * 64 + row) * ldo + seg * 64;
#pragma unroll
        for (int q = 0; q < 8; ++q) {
            __nv_bfloat162 hv[4], lv[4];
#pragma unroll
            for (int j = 0; j < 4; ++j) {
                float a = sp[q * 8 + 2 * j], c2 = sp[q * 8 + 2 * j + 1];
                __nv_bfloat16 ha = __float2bfloat16(a), hc = __float2bfloat16(c2);
                hv[j].x = ha; hv[j].y = hc;
                lv[j].x = __float2bfloat16(a - __bfloat162float(ha));
                lv[j].y = __float2bfloat16(c2 - __bfloat162float(hc));
            }
            *(uint4*)(dh + o + q * 8) = *(uint4*)hv;
            *(uint4*)(dl + o + q * 8) = *(uint4*)lv;
        }
    }
}

/* ---------------- GEMM1: ec[n][d] (hi/lo) = ext[n][:] . We[d][:] ---------------- */
__global__ __launch_bounds__(NTHR, 2) void k_g1()
{
    extern __shared__ __align__(128) char sm[];
    uint32_t smu = s2u(sm);
    int b = blockIdx.z, r0 = blockIdx.y * 128, c0 = blockIdx.x * 128;
    FragC acc[4][4];
    size_t ao = ((size_t)b * HW + r0) * CCH;
    gemm_core<false>(sm, smu, g_ext_h + ao, g_ext_l + ao, CCH,
              g_We_h + (size_t)c0 * CCH, g_We_l + (size_t)c0 * CCH,
              g_We_h + (size_t)c0 * CCH, g_We_l + (size_t)c0 * CCH, 1 << 30, CCH, CCH, acc);
    epilogue_split(sm, acc, g_ec_h, g_ec_l, ao + c0, CCH);
}

/* ---- GEMM2 + fused epilogue: E=__expf(ec.qt^T); En hi/lo; row/col sums ---- */
__global__ __launch_bounds__(NTHR, 2) void k_g2()
{
    extern __shared__ __align__(128) char sm[];
    uint32_t smu = s2u(sm);
    int b = blockIdx.z, r0 = blockIdx.y * 128, c0 = blockIdx.x * 128;
    int t = threadIdx.x, wid = t >> 5, wm = wid >> 1, wn = wid & 1;
    FragC acc[4][4];
    size_t ao = ((size_t)b * HW + r0) * CCH, bo = ((size_t)b * HW + c0) * CCH;
    gemm_core<false>(sm, smu, g_ec_h + ao, g_ec_l + ao, CCH,
              g_qt_h + bo, g_qt_l + bo, g_qt_h + bo, g_qt_l + bo, 1 << 30, CCH, CCH, acc);

#pragma unroll
    for (int mf = 0; mf < 4; ++mf)
#pragma unroll
        for (int nf = 0; nf < 4; ++nf)
#pragma unroll
            for (int i = 0; i < acc[mf][nf].num_elements; ++i)
                acc[mf][nf].x[i] = __expf(acc[mf][nf].x[i]);

    float* stg = (float*)sm;
    const int LDS2 = 132;
    float csum = 0.f;
    for (int h = 0; h < 2; ++h) {
        __syncthreads();
        if (wm == h) {
#pragma unroll
            for (int mf = 0; mf < 4; ++mf)
#pragma unroll
                for (int nf = 0; nf < 4; ++nf)
                    wmma::store_matrix_sync(stg + (mf * 16) * LDS2 + wn * 64 + nf * 16,
                                            acc[mf][nf], LDS2, wmma::mem_row_major);
        }
        __syncthreads();
        {
            int row = t >> 1, seg = t & 1;
            const float* sp = stg + row * LDS2 + seg * 64;
            size_t o = ((size_t)b * HW + r0 + h * 64 + row) * HW + c0 + seg * 64;
            float rs = 0.f;
#pragma unroll
            for (int q = 0; q < 8; ++q) {
                __nv_bfloat162 hv[4], lv[4];
#pragma unroll
                for (int j = 0; j < 4; ++j) {
                    float a = sp[q * 8 + 2 * j], c2 = sp[q * 8 + 2 * j + 1];
                    rs += a + c2;
                    __nv_bfloat16 ha = __float2bfloat16(a), hc = __float2bfloat16(c2);
                    hv[j].x = ha; hv[j].y = hc;
                    lv[j].x = __float2bfloat16(a - __bfloat162float(ha));
                    lv[j].y = __float2bfloat16(c2 - __bfloat162float(hc));
                }
                *(uint4*)(g_En_h + o + q * 8) = *(uint4*)hv;
                *(uint4*)(g_En_l + o + q * 8) = *(uint4*)lv;
            }
            rs += __shfl_xor_sync(~0u, rs, 1);
            if (seg == 0) atomicAdd(&g_rowsum[b * HW + r0 + h * 64 + row], rs);
        }
        {
            const float* sp = stg + t;
#pragma unroll
            for (int j = 0; j < 64; ++j) csum += sp[j * LDS2];
        }
    }
    atomicAdd(&g_colsum[b * HW + c0 + t], csum);
}

/* ------ GEMM3/4 merged (both read only En): z -> (b, sel) ------ */
__global__ __launch_bounds__(NTHR, 2) void k_att()
{
    extern __shared__ __align__(128) char sm[];
    uint32_t smu = s2u(sm);
    int z = blockIdx.z, b = z >> 1, sel = z & 1;
    FragC acc[4][4];
    if (sel == 1) {
        int r0 = blockIdx.y * 128, c0 = blockIdx.x * 128;
        size_t ao = ((size_t)b * HW + r0) * HW, bo = ((size_t)b * CCH + c0) * HW;
        gemm_core<false>(sm, smu, g_En_h + ao, g_En_l + ao, HW,
                  g_q_h + bo, g_q_l + bo, g_q_h + bo, g_q_l + bo, 1 << 30, HW, HW, acc);
        __syncthreads();
        store_c(acc, g_eattF + ((size_t)b * HW + r0) * CCH + c0, CCH);
    } else {
        int cblk = blockIdx.x * 128, m0 = blockIdx.y * 128;
        size_t ao = ((size_t)b * CCH + cblk) * HW;
        const __nv_bfloat16* Bh = g_En_h + (size_t)b * HW * HW + m0;
        const __nv_bfloat16* Bl = g_En_l + (size_t)b * HW * HW + m0;
        gemm_core<true>(sm, smu, g_ex_h + ao, g_ex_l + ao, HW,
                  Bh, Bl, Bh, Bl, 1 << 30, HW, HW, acc);
        __syncthreads();
        store_c_col(acc, g_qattF + ((size_t)b * HW + m0) * CCH + cblk, CCH);
    }
}

/* ------ conv merged: out[o][x] = W[o][0:512].[att|inp_t][x][0:512]; z -> (b, w) ------ */
__global__ __launch_bounds__(NTHR, 2) void k_conv(float* __restrict__ out)
{
    extern __shared__ __align__(128) char sm[];
    uint32_t smu = s2u(sm);
    int z = blockIdx.z, b = z >> 1, w = z & 1;
    int o0 = blockIdx.y * 128, x0 = blockIdx.x * 128;
    const __nv_bfloat16 *Wh, *Wl, *B1h, *B1l, *B2h, *B2l;
    if (w == 0) { Wh = g_W1_h; Wl = g_W1_l; B1h = g_eatt_h; B1l = g_eatt_l; B2h = g_ext_h; B2l = g_ext_l; }
    else        { Wh = g_W2_h; Wl = g_W2_l; B1h = g_qatt_h; B1l = g_qatt_l; B2h = g_qt_h;  B2l = g_qt_l; }
    FragC acc[4][4];
    size_t bo = ((size_t)b * HW + x0) * CCH;
    gemm_core<false>(sm, smu, Wh + (size_t)o0 * 512, Wl + (size_t)o0 * 512, 512,
              B1h + bo, B1l + bo, B2h + bo, B2l + bo, 256, CCH, 512, acc);
    __syncthreads();
    store_c(acc, out + (size_t)w * SZ_CN + ((size_t)b * CCH + o0) * HW + x0, HW);
}

/* ---------------- ew3 merged: normalize + gate + split; y -> sel ---------------- */
__global__ __launch_bounds__(256) void k_ew3(const float* __restrict__ gw)
{
    __shared__ float sgw[256];
    int tid = threadIdx.x, lane = tid & 31, wid = tid >> 5;
    int sel = blockIdx.y;
    sgw[tid] = gw[tid];
    __syncthreads();
    const float* af = sel ? g_eattF : g_qattF;
    const float* sums = sel ? g_rowsum : g_colsum;
    __nv_bfloat16* oh = sel ? g_eatt_h : g_qatt_h;
    __nv_bfloat16* ol = sel ? g_eatt_l : g_qatt_l;
    size_t row = (size_t)blockIdx.x * 8 + wid;
    float4 v0 = *(const float4*)(af + row * 256 + lane * 8);
    float4 v1 = *(const float4*)(af + row * 256 + lane * 8 + 4);
    float v[8] = {v0.x, v0.y, v0.z, v0.w, v1.x, v1.y, v1.z, v1.w};
    float dot = 0.f;
#pragma unroll
    for (int j = 0; j < 8; ++j) dot += v[j] * sgw[lane * 8 + j];
#pragma unroll
    for (int m = 16; m; m >>= 1) dot += __shfl_xor_sync(~0u, dot, m);
    float inv = 1.f / sums[row];
    float s = inv / (1.f + expf(-inv * dot));
    __nv_bfloat162 hq[4], lq[4];
#pragma unroll
    for (int j = 0; j < 4; ++j) {
        float a = v[2 * j] * s, c = v[2 * j + 1] * s;
        __nv_bfloat16 ha = __float2bfloat16(a), hc = __float2bfloat16(c);
        hq[j].x = ha; hq[j].y = hc;
        lq[j].x = __float2bfloat16(a - __bfloat162float(ha));
        lq[j].y = __float2bfloat16(c - __bfloat162float(hc));
    }
    *(uint4*)(oh + row * 256 + lane * 8) = *(uint4*)hq;
    *(uint4*)(ol + row * 256 + lane * 8) = *(uint4*)lq;
}

/* ---------------- prep1: ALL linear splits + zero, one launch ---------------- */
#define N2IN ((int)(SZ_CN / 2))
__global__ void k_prep1(const float* __restrict__ in1, const float* __restrict__ in2,
                        const float* __restrict__ We, const float* __restrict__ W1,
                        const float* __restrict__ W2)
{
    int idx = blockIdx.x * 256 + threadIdx.x;
    const float* src; __nv_bfloat16 *dh, *dl; int i = idx;
    if (idx < N2IN)                         { src = in1; dh = g_ex_h; dl = g_ex_l; }
    else if ((i -= N2IN) < N2IN)            { src = in2; dh = g_q_h;  dl = g_q_l;  }
    else if ((i -= N2IN) < CCH*CCH/2)       { src = We;  dh = g_We_h; dl = g_We_l; }
    else if ((i -= CCH*CCH/2) < CCH*CCH)    { src = W1;  dh = g_W1_h; dl = g_W1_l; }
    else if ((i -= CCH*CCH) < CCH*CCH)      { src = W2;  dh = g_W2_h; dl = g_W2_l; }
    else {
        i -= CCH*CCH;
        if (i < NB * HW) { g_colsum[i] = 0.f; g_rowsum[i] = 0.f; }
        return;
    }
    float2 v = ((const float2*)src)[i];
    __nv_bfloat16 h0 = __float2bfloat16(v.x), h1 = __float2bfloat16(v.y);
    __nv_bfloat162 hp, lp;
    hp.x = h0; hp.y = h1;
    lp.x = __float2bfloat16(v.x - __bfloat162float(h0));
    lp.y = __float2bfloat16(v.y - __bfloat162float(h1));
    ((__nv_bfloat162*)dh)[i] = hp;
    ((__nv_bfloat162*)dl)[i] = lp;
}
#define PREP1_TOTAL (2 * N2IN + CCH*CCH/2 + 2 * CCH*CCH + NB * HW)

/* ---------------- tsplit both inputs: z = sel*NB + b ---------------- */
__global__ void k_tsplit(const float* __restrict__ in1, const float* __restrict__ in2)
{
    __shared__ float t[32][33];
    int z = blockIdx.z, sel = z / NB, b = z % NB;
    const float* src = sel ? in2 : in1;
    __nv_bfloat16* dh = sel ? g_qt_h : g_ext_h;
    __nv_bfloat16* dl = sel ? g_qt_l : g_ext_l;
    int c0 = blockIdx.y * 32, n0 = blockIdx.x * 32;
    int tx = threadIdx.x, ty = threadIdx.y;
#pragma unroll
    for (int i = 0; i < 4; ++i)
        t[ty + i * 8][tx] = src[((size_t)b * CCH + c0 + ty + i * 8) * HW + n0 + tx];
    __syncthreads();
#pragma unroll
    for (int i = 0; i < 4; ++i) {
        float v = t[tx][ty + i * 8];
        size_t o = ((size_t)b * HW + n0 + ty + i * 8) * CCH + c0 + tx;
        __nv_bfloat16 h = __float2bfloat16(v);
        dh[o] = h;
        dl[o] = __float2bfloat16(v - __bfloat162float(h));
    }
}

/* ---------------- launch ---------------- */
extern "C" void kernel_launch(void* const* d_in, const int* in_sizes, int n_in,
                              void* d_out, int out_size)
{
    const float* in1 = (const float*)d_in[0];
    const float* in2 = (const float*)d_in[1];
    const float* We  = (const float*)d_in[2];
    const float* gw  = (const float*)d_in[3];
    const float* W1  = (const float*)d_in[4];
    const float* W2  = (const float*)d_in[5];
    float* out = (float*)d_out;

    cudaFuncSetAttribute(k_g1,   cudaFuncAttributeMaxDynamicSharedMemorySize, SM_GEMM);
    cudaFuncSetAttribute(k_g2,   cudaFuncAttributeMaxDynamicSharedMemorySize, SM_GEMM);
    cudaFuncSetAttribute(k_att,  cudaFuncAttributeMaxDynamicSharedMemorySize, SM_GEMM);
    cudaFuncSetAttribute(k_conv, cudaFuncAttributeMaxDynamicSharedMemorySize, SM_GEMM);

    k_prep1<<<(PREP1_TOTAL + 255) / 256, 256>>>(in1, in2, We, W1, W2);           /* #1 */
    k_tsplit<<<dim3(HW / 32, CCH / 32, NB * 2), dim3(32, 8)>>>(in1, in2);        /* #2 */
    k_g1<<<dim3(CCH / 128, HW / 128, NB), NTHR, SM_GEMM>>>();                    /* #3 */
    k_g2<<<dim3(HW / 128, HW / 128, NB), NTHR, SM_GEMM>>>();                     /* #4 <- ncu */
    k_att<<<dim3(CCH / 128, HW / 128, NB * 2), NTHR, SM_GEMM>>>();               /* #5 */
    k_ew3<<<dim3(NB * HW / 8, 2), 256>>>(gw);                                    /* #6 */
    k_conv<<<dim3(HW / 128, CCH / 128, NB * 2), NTHR, SM_GEMM>>>(out);           /* #7 */
}